// round 1
// baseline (speedup 1.0000x reference)
#include <cuda_runtime.h>
#include <math.h>

#define SEQ 4096
#define IND 1024
#define NH  16
#define HD  64
#define ODIM (NH * HD)   // 1024

// Scratch for projected Q/K/V, laid out [head][seq][HD]
__device__ float g_Q[NH * SEQ * HD];
__device__ float g_K[NH * SEQ * HD];
__device__ float g_V[NH * SEQ * HD];

// ---------------------------------------------------------------------------
// Kernel 1: QKV projection GEMM.  C[s, n] = sum_k H[s,k] * W[k,n] + bias[n]
// Tile: 64x64 output, BK=16.  256 threads, each computes a 4x4 micro-tile.
// blockIdx.x = head (64-wide N tile == one head), blockIdx.y = seq tile,
// blockIdx.z selects which of Wq/Wk/Wv.
// Output written directly in [head][seq][HD] layout.
// ---------------------------------------------------------------------------
__global__ __launch_bounds__(256) void qkv_gemm(
    const float* __restrict__ H,
    const float* __restrict__ Wq, const float* __restrict__ Wk,
    const float* __restrict__ Wv,
    const float* __restrict__ Bq, const float* __restrict__ Bk,
    const float* __restrict__ Bv)
{
    __shared__ float As[16][64];   // As[k][m]  (A transposed)
    __shared__ float Bs[16][64];   // Bs[k][n]

    const float* W; const float* Bias; float* Out;
    if (blockIdx.z == 0)      { W = Wq; Bias = Bq; Out = g_Q; }
    else if (blockIdx.z == 1) { W = Wk; Bias = Bk; Out = g_K; }
    else                      { W = Wv; Bias = Bv; Out = g_V; }

    const int tid  = threadIdx.x;
    const int r0   = (tid >> 4) * 4;      // row in 64-tile
    const int c0   = (tid & 15) * 4;      // col in 64-tile
    const int head = blockIdx.x;
    const int n0   = head * 64;
    const int s0   = blockIdx.y * 64;

    // load mapping
    const int lrA = tid >> 2;             // 0..63 : A row
    const int lcA = (tid & 3) * 4;        // 0,4,8,12 : A k-chunk
    const int lrB = tid >> 4;             // 0..15 : B k-row
    const int lcB = (tid & 15) * 4;       // B n-chunk

    const float* hptr = H + (s0 + lrA) * IND + lcA;
    const float* wptr = W + lrB * ODIM + n0 + lcB;

    float acc[4][4];
#pragma unroll
    for (int i = 0; i < 4; i++)
#pragma unroll
        for (int j = 0; j < 4; j++) acc[i][j] = 0.0f;

    for (int k0 = 0; k0 < IND; k0 += 16) {
        float4 a = *(const float4*)(hptr + k0);
        float4 b = *(const float4*)(wptr + (size_t)k0 * ODIM);
        __syncthreads();
        As[lcA + 0][lrA] = a.x;
        As[lcA + 1][lrA] = a.y;
        As[lcA + 2][lrA] = a.z;
        As[lcA + 3][lrA] = a.w;
        *(float4*)&Bs[lrB][lcB] = b;
        __syncthreads();
#pragma unroll
        for (int kk = 0; kk < 16; kk++) {
            float4 av = *(const float4*)&As[kk][r0];
            float4 bv = *(const float4*)&Bs[kk][c0];
            float ar[4] = {av.x, av.y, av.z, av.w};
            float br[4] = {bv.x, bv.y, bv.z, bv.w};
#pragma unroll
            for (int i = 0; i < 4; i++)
#pragma unroll
                for (int j = 0; j < 4; j++)
                    acc[i][j] = fmaf(ar[i], br[j], acc[i][j]);
        }
    }

    float4 bias = *(const float4*)(Bias + n0 + c0);
#pragma unroll
    for (int i = 0; i < 4; i++) {
        float4 r;
        r.x = acc[i][0] + bias.x;
        r.y = acc[i][1] + bias.y;
        r.z = acc[i][2] + bias.z;
        r.w = acc[i][3] + bias.w;
        *(float4*)&Out[((size_t)head * SEQ + s0 + r0 + i) * HD + c0] = r;
    }
}

// ---------------------------------------------------------------------------
// Kernel 2: flash attention.  One block = (head, 64-query tile).
// 256 threads, 4x4 register tiles.  K smem buffer is reused for the P tile
// (valid: all K reads complete before P writes, separated by __syncthreads).
// Static smem = 3 * 64*64*4 = 48KB exactly -> 4 CTAs/SM.
// ---------------------------------------------------------------------------
__global__ __launch_bounds__(256) void attn_kernel(float* __restrict__ Out)
{
    __shared__ float Qs[64 * 64];   // Qs[d*64 + r]   (transposed, pre-scaled)
    __shared__ float KP[64 * 64];   // Kts[d*64 + c]  then  P[r*64 + t]
    __shared__ float Vs[64 * 64];   // Vs[t*64 + d]

    const int tid  = threadIdx.x;
    const int head = blockIdx.y;
    const int qt   = blockIdx.x;
    const int r0   = (tid >> 4) * 4;   // query rows owned
    const int c0   = (tid & 15) * 4;   // key cols / out dims owned
    const int lr   = tid >> 2;         // load row 0..63
    const int lc4  = (tid & 3) * 4;    // load d-chunk base

    const float* Qg = g_Q + ((size_t)head * SEQ + qt * 64) * HD;
    const float* Kg = g_K + (size_t)head * SEQ * HD;
    const float* Vg = g_V + (size_t)head * SEQ * HD;

    // Load Q tile transposed into smem, folding in the 1/sqrt(64) scale.
#pragma unroll
    for (int it = 0; it < 4; it++) {
        int d = lc4 + it * 16;
        float4 q = *(const float4*)(Qg + lr * HD + d);
        Qs[(d + 0) * 64 + lr] = q.x * 0.125f;
        Qs[(d + 1) * 64 + lr] = q.y * 0.125f;
        Qs[(d + 2) * 64 + lr] = q.z * 0.125f;
        Qs[(d + 3) * 64 + lr] = q.w * 0.125f;
    }

    float o[4][4];
    float mrow[4], lrow[4];
#pragma unroll
    for (int i = 0; i < 4; i++) {
        mrow[i] = -INFINITY;
        lrow[i] = 0.0f;
#pragma unroll
        for (int j = 0; j < 4; j++) o[i][j] = 0.0f;
    }

    for (int kt = 0; kt < SEQ / 64; kt++) {
        __syncthreads();   // previous iteration's KP/Vs reads complete
        const float* Kt = Kg + (size_t)kt * 64 * HD;
        const float* Vt = Vg + (size_t)kt * 64 * HD;
#pragma unroll
        for (int it = 0; it < 4; it++) {
            int d = lc4 + it * 16;
            float4 k = *(const float4*)(Kt + lr * HD + d);
            KP[(d + 0) * 64 + lr] = k.x;
            KP[(d + 1) * 64 + lr] = k.y;
            KP[(d + 2) * 64 + lr] = k.z;
            KP[(d + 3) * 64 + lr] = k.w;
            float4 v = *(const float4*)(Vt + lr * HD + d);
            *(float4*)&Vs[lr * 64 + d] = v;
        }
        __syncthreads();

        // S = (Q * scale) K^T   -- 64-deep dot products
        float s[4][4];
#pragma unroll
        for (int i = 0; i < 4; i++)
#pragma unroll
            for (int j = 0; j < 4; j++) s[i][j] = 0.0f;

#pragma unroll 16
        for (int d = 0; d < 64; d++) {
            float4 qv = *(const float4*)&Qs[d * 64 + r0];
            float4 kv = *(const float4*)&KP[d * 64 + c0];
            float qa[4] = {qv.x, qv.y, qv.z, qv.w};
            float ka[4] = {kv.x, kv.y, kv.z, kv.w};
#pragma unroll
            for (int i = 0; i < 4; i++)
#pragma unroll
                for (int j = 0; j < 4; j++)
                    s[i][j] = fmaf(qa[i], ka[j], s[i][j]);
        }

        // Online softmax.  Row stats reduced across the 16 tx lanes
        // (xor masks 1,2,4,8 stay inside the 16-lane half-warp group).
#pragma unroll
        for (int i = 0; i < 4; i++) {
            float mx = fmaxf(fmaxf(s[i][0], s[i][1]), fmaxf(s[i][2], s[i][3]));
            mx = fmaxf(mx, __shfl_xor_sync(0xffffffffu, mx, 1));
            mx = fmaxf(mx, __shfl_xor_sync(0xffffffffu, mx, 2));
            mx = fmaxf(mx, __shfl_xor_sync(0xffffffffu, mx, 4));
            mx = fmaxf(mx, __shfl_xor_sync(0xffffffffu, mx, 8));
            float mnew = fmaxf(mrow[i], mx);
            float corr = __expf(mrow[i] - mnew);
            mrow[i] = mnew;
            float sum = 0.0f;
#pragma unroll
            for (int j = 0; j < 4; j++) {
                float p = __expf(s[i][j] - mnew);
                s[i][j] = p;
                sum += p;
            }
            sum += __shfl_xor_sync(0xffffffffu, sum, 1);
            sum += __shfl_xor_sync(0xffffffffu, sum, 2);
            sum += __shfl_xor_sync(0xffffffffu, sum, 4);
            sum += __shfl_xor_sync(0xffffffffu, sum, 8);
            lrow[i] = lrow[i] * corr + sum;
            o[i][0] *= corr; o[i][1] *= corr; o[i][2] *= corr; o[i][3] *= corr;
        }

        __syncthreads();   // all Kts reads done -> safe to overwrite with P
#pragma unroll
        for (int i = 0; i < 4; i++)
            *(float4*)&KP[(r0 + i) * 64 + c0] =
                make_float4(s[i][0], s[i][1], s[i][2], s[i][3]);
        __syncthreads();

        // O += P V
#pragma unroll 8
        for (int t = 0; t < 64; t++) {
            float4 vv = *(const float4*)&Vs[t * 64 + c0];
            float va[4] = {vv.x, vv.y, vv.z, vv.w};
            float p0 = KP[(r0 + 0) * 64 + t];
            float p1 = KP[(r0 + 1) * 64 + t];
            float p2 = KP[(r0 + 2) * 64 + t];
            float p3 = KP[(r0 + 3) * 64 + t];
#pragma unroll
            for (int j = 0; j < 4; j++) {
                o[0][j] = fmaf(p0, va[j], o[0][j]);
                o[1][j] = fmaf(p1, va[j], o[1][j]);
                o[2][j] = fmaf(p2, va[j], o[2][j]);
                o[3][j] = fmaf(p3, va[j], o[3][j]);
            }
        }
    }

    // Normalize and write out: Out[s][head*64 + d]
#pragma unroll
    for (int i = 0; i < 4; i++) {
        float inv = 1.0f / lrow[i];
        float4 r = make_float4(o[i][0] * inv, o[i][1] * inv,
                               o[i][2] * inv, o[i][3] * inv);
        int row = qt * 64 + r0 + i;
        *(float4*)&Out[(size_t)row * ODIM + head * HD + c0] = r;
    }
}

// ---------------------------------------------------------------------------
extern "C" void kernel_launch(void* const* d_in, const int* in_sizes, int n_in,
                              void* d_out, int out_size)
{
    const float* h  = (const float*)d_in[0];
    const float* Wq = (const float*)d_in[1];
    const float* Wk = (const float*)d_in[2];
    const float* Wv = (const float*)d_in[3];
    const float* bq = (const float*)d_in[4];
    const float* bk = (const float*)d_in[5];
    const float* bv = (const float*)d_in[6];
    float* out = (float*)d_out;

    dim3 gemm_grid(NH, SEQ / 64, 3);
    qkv_gemm<<<gemm_grid, 256>>>(h, Wq, Wk, Wv, bq, bk, bv);

    dim3 attn_grid(SEQ / 64, NH);
    attn_kernel<<<attn_grid, 256>>>(out);
}